// round 7
// baseline (speedup 1.0000x reference)
#include <cuda_runtime.h>

// Smoother: out = max(pred, (moving_sum_501(reflect_pad_T(pred)) + bias) / 501)
// pred: [B=8, T=16384, C=128] fp32, bias: [1] fp32, out: same shape.
//
// R5: same float4 / one-warp-per-(batch,segment) decomposition as R4, but
// restructured for memory-level parallelism (the R4 profile showed pure
// latency exposure: DRAM 20%, issue 11.6%, occ 9.7%):
//   - __launch_bounds__(32, 1): allow high register use (block-count caps
//     occupancy at ~7 warps/SM regardless; registers are free).
//   - init loop: explicit 16-wide LDG.128 batches (8 KB in flight/warp).
//   - steady loop: explicit 8-iteration batch of lead/trail/mid loads
//     (24 independent LDG.128 = 12 KB in flight) before any use.

#define Bn   8
#define Tn   16384
#define C4   32            // 128 channels / 4 per float4
#define Kn   501
#define Pn   250
#define SEG  128
#define NSEG (Tn / SEG)    // 128

__device__ __forceinline__ int refl(int k) {
    if (k < 0) k = -k;
    if (k >= Tn) k = 2 * Tn - 2 - k;
    return k;
}

__device__ __forceinline__ void acc4(float4& a, const float4 v) {
    a.x += v.x; a.y += v.y; a.z += v.z; a.w += v.w;
}

__global__ void __launch_bounds__(32, 1) smoother_kernel(
    const float4* __restrict__ pred,
    const float*  __restrict__ bias,
    float4*       __restrict__ out)
{
    const int c  = threadIdx.x;     // float4 channel group 0..31
    const int s  = blockIdx.x;      // T segment 0..NSEG-1
    const int b  = blockIdx.y;      // batch 0..7
    const int t0 = s * SEG;

    const float4* p = pred + (size_t)b * Tn * C4 + c;
    float4*       o = out  + (size_t)b * Tn * C4 + c;

    const float bv  = bias[0];
    const float inv = 1.0f / (float)Kn;

    float4 W;

    // Fast path iff full footprint [t0-Pn, t0+SEG+Pn] is in [0, Tn-1].
    const bool fast = (t0 >= Pn) && (t0 + SEG + Pn + 1 <= Tn);

    if (fast) {
        // ---- init: W = sum_{k=0}^{500} q[k], 16-wide load batches ----
        const float4* q = p + (t0 - Pn) * C4;
        float4 a0 = make_float4(0.f, 0.f, 0.f, 0.f);
        float4 a1 = make_float4(0.f, 0.f, 0.f, 0.f);
        float4 a2 = make_float4(0.f, 0.f, 0.f, 0.f);
        float4 a3 = make_float4(0.f, 0.f, 0.f, 0.f);
        int k = 0;
        for (; k + 16 <= Kn; k += 16) {           // 31 batches of 16
            float4 r[16];
            #pragma unroll
            for (int j = 0; j < 16; j++) r[j] = q[(k + j) * C4];
            #pragma unroll
            for (int j = 0; j < 16; j += 4) {
                acc4(a0, r[j + 0]);
                acc4(a1, r[j + 1]);
                acc4(a2, r[j + 2]);
                acc4(a3, r[j + 3]);
            }
        }
        for (; k < Kn; k++) acc4(a0, q[k * C4]);  // tail: 5
        W.x = (a0.x + a1.x) + (a2.x + a3.x);
        W.y = (a0.y + a1.y) + (a2.y + a3.y);
        W.z = (a0.z + a1.z) + (a2.z + a3.z);
        W.w = (a0.w + a1.w) + (a2.w + a3.w);

        const float4* lead  = p + (t0 + Pn + 1) * C4;
        const float4* trail = p + (t0 - Pn) * C4;
        const float4* mid   = p + t0 * C4;
        float4*       op    = o + t0 * C4;

        // ---- steady: batches of 8 outputs, 24 loads issued up front ----
        for (int ii = 0; ii < SEG; ii += 8) {
            float4 L[8], Tt[8], M[8];
            #pragma unroll
            for (int j = 0; j < 8; j++) {
                L[j]  = lead [(ii + j) * C4];
                Tt[j] = trail[(ii + j) * C4];
                M[j]  = mid  [(ii + j) * C4];
            }
            #pragma unroll
            for (int j = 0; j < 8; j++) {
                float4 r;
                r.x = fmaxf(M[j].x, (W.x + bv) * inv);
                r.y = fmaxf(M[j].y, (W.y + bv) * inv);
                r.z = fmaxf(M[j].z, (W.z + bv) * inv);
                r.w = fmaxf(M[j].w, (W.w + bv) * inv);
                op[(ii + j) * C4] = r;
                W.x += L[j].x - Tt[j].x;
                W.y += L[j].y - Tt[j].y;
                W.z += L[j].z - Tt[j].z;
                W.w += L[j].w - Tt[j].w;
            }
        }
    } else {
        // ---- boundary path: reflected indices throughout ----
        W = make_float4(0.f, 0.f, 0.f, 0.f);
        for (int k = t0 - Pn; k <= t0 + Pn; k++)
            acc4(W, p[refl(k) * C4]);

        for (int i = 0; i < SEG; i++) {
            int t = t0 + i;
            float4 m = p[t * C4];
            float4 r;
            r.x = fmaxf(m.x, (W.x + bv) * inv);
            r.y = fmaxf(m.y, (W.y + bv) * inv);
            r.z = fmaxf(m.z, (W.z + bv) * inv);
            r.w = fmaxf(m.w, (W.w + bv) * inv);
            o[t * C4] = r;
            float4 l  = p[refl(t + Pn + 1) * C4];
            float4 tr = p[refl(t - Pn) * C4];
            W.x += l.x - tr.x;
            W.y += l.y - tr.y;
            W.z += l.z - tr.z;
            W.w += l.w - tr.w;
        }
    }
}

extern "C" void kernel_launch(void* const* d_in, const int* in_sizes, int n_in,
                              void* d_out, int out_size)
{
    const float4* pred = (const float4*)d_in[0];
    const float*  bias = (const float*)d_in[1];
    float4*       out  = (float4*)d_out;

    (void)in_sizes; (void)n_in; (void)out_size;

    dim3 grid(NSEG, Bn);   // 128 x 8 = 1024 single-warp blocks
    dim3 block(32);
    smoother_kernel<<<grid, block>>>(pred, bias, out);
}

// round 8
// speedup vs baseline: 1.2356x; 1.2356x over previous
#include <cuda_runtime.h>

// Smoother: out = max(pred, (moving_sum_501(reflect_pad_T(pred)) + bias) / 501)
// pred: [B=8, T=16384, C=128] fp32, bias: [1] fp32, out: same shape.
//
// R7: two-kernel design.
//  K1: 32-row tile sums TS[b][j][c] (512 tiles, 4096 warps, streaming reduce).
//  K2: sliding-window main kernel, SEG=64 -> 2048 warps. Window init uses
//      26 edge rows + 14 tile sums + 27 edge rows (constant split since
//      t0 = 64s => (t0-250) mod 32 == 6) instead of 501 row loads.
//      R4/R5 profiling showed the 501-load per-warp init serial chain at only
//      ~7 warps/SM was the bottleneck (DRAM 20%, issue <16%).

#define Bn   8
#define Tn   16384
#define C4   32            // 128 channels / 4 per float4
#define Kn   501
#define Pn   250
#define SEG  64
#define NSEG (Tn / SEG)    // 256
#define TILE 32
#define NT   (Tn / TILE)   // 512

// tile-sum scratch: 8 * 512 * 32 float4 = 2 MB
__device__ float4 g_TS[Bn * NT * C4];

__device__ __forceinline__ int refl(int k) {
    if (k < 0) k = -k;
    if (k >= Tn) k = 2 * Tn - 2 - k;
    return k;
}

__device__ __forceinline__ void acc4(float4& a, const float4 v) {
    a.x += v.x; a.y += v.y; a.z += v.z; a.w += v.w;
}

// ---------------------------------------------------------------- kernel 1
__global__ void __launch_bounds__(32, 1) tile_sum_kernel(
    const float4* __restrict__ pred)
{
    const int c = threadIdx.x;      // float4 lane
    const int j = blockIdx.x;       // tile 0..NT-1
    const int b = blockIdx.y;       // batch

    const float4* p = pred + (size_t)b * Tn * C4 + (size_t)j * TILE * C4 + c;

    float4 a0 = make_float4(0.f, 0.f, 0.f, 0.f);
    float4 a1 = make_float4(0.f, 0.f, 0.f, 0.f);
    float4 a2 = make_float4(0.f, 0.f, 0.f, 0.f);
    float4 a3 = make_float4(0.f, 0.f, 0.f, 0.f);

    float4 r[16];
    #pragma unroll
    for (int u = 0; u < 16; u++) r[u] = p[u * C4];
    #pragma unroll
    for (int u = 0; u < 16; u += 4) {
        acc4(a0, r[u + 0]); acc4(a1, r[u + 1]);
        acc4(a2, r[u + 2]); acc4(a3, r[u + 3]);
    }
    #pragma unroll
    for (int u = 0; u < 16; u++) r[u] = p[(16 + u) * C4];
    #pragma unroll
    for (int u = 0; u < 16; u += 4) {
        acc4(a0, r[u + 0]); acc4(a1, r[u + 1]);
        acc4(a2, r[u + 2]); acc4(a3, r[u + 3]);
    }

    float4 s;
    s.x = (a0.x + a1.x) + (a2.x + a3.x);
    s.y = (a0.y + a1.y) + (a2.y + a3.y);
    s.z = (a0.z + a1.z) + (a2.z + a3.z);
    s.w = (a0.w + a1.w) + (a2.w + a3.w);

    g_TS[((size_t)b * NT + j) * C4 + c] = s;
}

// ---------------------------------------------------------------- kernel 2
__global__ void __launch_bounds__(32, 1) smoother_kernel(
    const float4* __restrict__ pred,
    const float*  __restrict__ bias,
    float4*       __restrict__ out)
{
    const int c  = threadIdx.x;     // float4 lane 0..31
    const int s  = blockIdx.x;      // T segment 0..NSEG-1
    const int b  = blockIdx.y;      // batch
    const int t0 = s * SEG;

    const float4* p = pred + (size_t)b * Tn * C4 + c;
    float4*       o = out  + (size_t)b * Tn * C4 + c;

    const float bv  = bias[0];
    const float inv = 1.0f / (float)Kn;

    float4 W;

    // Fast path iff footprint [t0-Pn, t0+SEG+Pn] in [0, Tn-1] and tile
    // indices valid: s in [4, 251] for SEG=64.
    const bool fast = (t0 >= 256) && (t0 + SEG + Pn + 1 <= Tn);

    if (fast) {
        // ---- init: W = sum over [t0-250, t0+251) ----
        // (t0-250) mod 32 == 6 always -> 26 lo-edge rows, 14 full tiles,
        // 27 hi-edge rows:
        //   lo-edge: rows t0-250 .. t0-225
        //   tiles:   j = 2s-7 .. 2s+6   (rows t0-224 .. t0+223)
        //   hi-edge: rows t0+224 .. t0+250
        float4 a0 = make_float4(0.f, 0.f, 0.f, 0.f);
        float4 a1 = make_float4(0.f, 0.f, 0.f, 0.f);
        float4 a2 = make_float4(0.f, 0.f, 0.f, 0.f);
        float4 a3 = make_float4(0.f, 0.f, 0.f, 0.f);

        {
            const float4* qlo = p + (t0 - Pn) * C4;          // 26 rows
            const float4* qhi = p + (t0 + 224) * C4;         // 27 rows
            const float4* ts  = g_TS + ((size_t)b * NT + (2 * s - 7)) * C4 + c;

            #pragma unroll
            for (int u = 0; u < 26; u++) {
                float4 v = qlo[u * C4];
                if      ((u & 3) == 0) acc4(a0, v);
                else if ((u & 3) == 1) acc4(a1, v);
                else if ((u & 3) == 2) acc4(a2, v);
                else                   acc4(a3, v);
            }
            #pragma unroll
            for (int u = 0; u < 27; u++) {
                float4 v = qhi[u * C4];
                if      ((u & 3) == 0) acc4(a0, v);
                else if ((u & 3) == 1) acc4(a1, v);
                else if ((u & 3) == 2) acc4(a2, v);
                else                   acc4(a3, v);
            }
            #pragma unroll
            for (int u = 0; u < 14; u++) {
                float4 v = ts[u * C4];
                if      ((u & 3) == 0) acc4(a0, v);
                else if ((u & 3) == 1) acc4(a1, v);
                else if ((u & 3) == 2) acc4(a2, v);
                else                   acc4(a3, v);
            }
        }
        W.x = (a0.x + a1.x) + (a2.x + a3.x);
        W.y = (a0.y + a1.y) + (a2.y + a3.y);
        W.z = (a0.z + a1.z) + (a2.z + a3.z);
        W.w = (a0.w + a1.w) + (a2.w + a3.w);

        const float4* lead  = p + (t0 + Pn + 1) * C4;
        const float4* trail = p + (t0 - Pn) * C4;
        const float4* mid   = p + t0 * C4;
        float4*       op    = o + t0 * C4;

        // ---- steady: 8 batches of 8 outputs ----
        for (int ii = 0; ii < SEG; ii += 8) {
            float4 L[8], Tt[8], M[8];
            #pragma unroll
            for (int j = 0; j < 8; j++) {
                L[j]  = lead [(ii + j) * C4];
                Tt[j] = trail[(ii + j) * C4];
                M[j]  = mid  [(ii + j) * C4];
            }
            #pragma unroll
            for (int j = 0; j < 8; j++) {
                float4 r;
                r.x = fmaxf(M[j].x, (W.x + bv) * inv);
                r.y = fmaxf(M[j].y, (W.y + bv) * inv);
                r.z = fmaxf(M[j].z, (W.z + bv) * inv);
                r.w = fmaxf(M[j].w, (W.w + bv) * inv);
                op[(ii + j) * C4] = r;
                W.x += L[j].x - Tt[j].x;
                W.y += L[j].y - Tt[j].y;
                W.z += L[j].z - Tt[j].z;
                W.w += L[j].w - Tt[j].w;
            }
        }
    } else {
        // ---- boundary path: reflected indices throughout ----
        float4 a0 = make_float4(0.f, 0.f, 0.f, 0.f);
        float4 a1 = make_float4(0.f, 0.f, 0.f, 0.f);
        float4 a2 = make_float4(0.f, 0.f, 0.f, 0.f);
        float4 a3 = make_float4(0.f, 0.f, 0.f, 0.f);
        int k = t0 - Pn;
        #pragma unroll 4
        for (; k + 4 <= t0 + Pn + 1; k += 4) {
            acc4(a0, p[refl(k + 0) * C4]);
            acc4(a1, p[refl(k + 1) * C4]);
            acc4(a2, p[refl(k + 2) * C4]);
            acc4(a3, p[refl(k + 3) * C4]);
        }
        for (; k <= t0 + Pn; k++) acc4(a0, p[refl(k) * C4]);
        W.x = (a0.x + a1.x) + (a2.x + a3.x);
        W.y = (a0.y + a1.y) + (a2.y + a3.y);
        W.z = (a0.z + a1.z) + (a2.z + a3.z);
        W.w = (a0.w + a1.w) + (a2.w + a3.w);

        for (int i = 0; i < SEG; i++) {
            int t = t0 + i;
            float4 m = p[t * C4];
            float4 r;
            r.x = fmaxf(m.x, (W.x + bv) * inv);
            r.y = fmaxf(m.y, (W.y + bv) * inv);
            r.z = fmaxf(m.z, (W.z + bv) * inv);
            r.w = fmaxf(m.w, (W.w + bv) * inv);
            o[t * C4] = r;
            float4 l  = p[refl(t + Pn + 1) * C4];
            float4 tr = p[refl(t - Pn) * C4];
            W.x += l.x - tr.x;
            W.y += l.y - tr.y;
            W.z += l.z - tr.z;
            W.w += l.w - tr.w;
        }
    }
}

extern "C" void kernel_launch(void* const* d_in, const int* in_sizes, int n_in,
                              void* d_out, int out_size)
{
    const float4* pred = (const float4*)d_in[0];
    const float*  bias = (const float*)d_in[1];
    float4*       out  = (float4*)d_out;

    (void)in_sizes; (void)n_in; (void)out_size;

    dim3 g1(NT, Bn);       // 512 x 8 tile-sum blocks
    dim3 g2(NSEG, Bn);     // 256 x 8 main blocks
    dim3 blk(32);
    tile_sum_kernel<<<g1, blk>>>(pred);
    smoother_kernel<<<g2, blk>>>(pred, bias, out);
}

// round 9
// speedup vs baseline: 1.8031x; 1.4592x over previous
#include <cuda_runtime.h>

// Smoother: out = max(pred, (moving_sum_501(reflect_pad_T(pred)) + bias) / 501)
// pred: [B=8, T=16384, C=128] fp32, bias: [1] fp32, out: same shape.
//
// R8: occupancy + boundary fix.
//  - 4 warps/block (one SEG=64 segment per warp), __launch_bounds__(128,4)
//    => regs <= 128, all 512 blocks resident (~16 warps/SM vs R7's 6).
//  - boundary segments: window init via contiguous range-sums (reflection
//    maps to a forward range) using tile sums => ~80 loads, not 501.
//  - steady loop: batch-4 load groups (12 independent LDG.128 in flight).

#define Bn   8
#define Tn   16384
#define C4   32            // 128 channels / 4 per float4
#define Kn   501
#define Pn   250
#define SEG  64
#define NSEG (Tn / SEG)    // 256
#define TILE 32
#define NT   (Tn / TILE)   // 512
#define WPB  4             // warps per block

// tile-sum scratch: 8 * 512 * 32 float4 = 2 MB
__device__ float4 g_TS[Bn * NT * C4];

__device__ __forceinline__ int refl(int k) {
    if (k < 0) k = -k;
    if (k >= Tn) k = 2 * Tn - 2 - k;
    return k;
}

__device__ __forceinline__ void acc4(float4& a, const float4 v) {
    a.x += v.x; a.y += v.y; a.z += v.z; a.w += v.w;
}

// ---------------------------------------------------------------- kernel 1
__global__ void __launch_bounds__(128) tile_sum_kernel(
    const float4* __restrict__ pred)
{
    const int c = threadIdx.x & 31;
    const int w = threadIdx.x >> 5;
    const int j = blockIdx.x * WPB + w;      // tile 0..NT-1
    const int b = blockIdx.y;

    const float4* p = pred + ((size_t)b * Tn + (size_t)j * TILE) * C4 + c;

    float4 a0 = make_float4(0.f, 0.f, 0.f, 0.f);
    float4 a1 = make_float4(0.f, 0.f, 0.f, 0.f);
    float4 a2 = make_float4(0.f, 0.f, 0.f, 0.f);
    float4 a3 = make_float4(0.f, 0.f, 0.f, 0.f);

    #pragma unroll
    for (int base = 0; base < TILE; base += 8) {
        float4 r[8];
        #pragma unroll
        for (int u = 0; u < 8; u++) r[u] = p[(base + u) * C4];
        #pragma unroll
        for (int u = 0; u < 8; u += 4) {
            acc4(a0, r[u + 0]); acc4(a1, r[u + 1]);
            acc4(a2, r[u + 2]); acc4(a3, r[u + 3]);
        }
    }

    float4 s;
    s.x = (a0.x + a1.x) + (a2.x + a3.x);
    s.y = (a0.y + a1.y) + (a2.y + a3.y);
    s.z = (a0.z + a1.z) + (a2.z + a3.z);
    s.w = (a0.w + a1.w) + (a2.w + a3.w);

    g_TS[((size_t)b * NT + j) * C4 + c] = s;
}

// Sum rows [lo, hi) of column p (stride C4) using tile sums ts where possible.
__device__ __forceinline__ void range_sum(
    const float4* __restrict__ p, const float4* __restrict__ ts,
    int lo, int hi, float4& W)
{
    int jlo = (lo + TILE - 1) / TILE;
    int jhi = hi / TILE;
    if (jhi > jlo) {
        for (int r = lo; r < jlo * TILE; r++) acc4(W, p[r * C4]);
        #pragma unroll 4
        for (int j = jlo; j < jhi; j++)       acc4(W, ts[j * C4]);
        for (int r = jhi * TILE; r < hi; r++) acc4(W, p[r * C4]);
    } else {
        for (int r = lo; r < hi; r++) acc4(W, p[r * C4]);
    }
}

// ---------------------------------------------------------------- kernel 2
__global__ void __launch_bounds__(128, 4) smoother_kernel(
    const float4* __restrict__ pred,
    const float*  __restrict__ bias,
    float4*       __restrict__ out)
{
    const int c  = threadIdx.x & 31;        // float4 lane
    const int w  = threadIdx.x >> 5;        // warp in block
    const int s  = blockIdx.x * WPB + w;    // segment 0..NSEG-1
    const int b  = blockIdx.y;
    const int t0 = s * SEG;

    const float4* p  = pred + (size_t)b * Tn * C4 + c;
    float4*       o  = out  + (size_t)b * Tn * C4 + c;
    const float4* ts = g_TS + (size_t)b * NT * C4 + c;

    const float bv  = bias[0];
    const float inv = 1.0f / (float)Kn;

    float4 W;

    // Fast path iff footprint [t0-Pn, t0+SEG+Pn] in [0, Tn-1] and tiles
    // 2s-7..2s+6 valid: s in [4, 251].
    const bool fast = (t0 >= 256) && (t0 + SEG + Pn + 1 <= Tn);

    if (fast) {
        // ---- init: 26 lo-edge rows + 14 tile sums + 27 hi-edge rows ----
        float4 a0 = make_float4(0.f, 0.f, 0.f, 0.f);
        float4 a1 = make_float4(0.f, 0.f, 0.f, 0.f);
        float4 a2 = make_float4(0.f, 0.f, 0.f, 0.f);
        float4 a3 = make_float4(0.f, 0.f, 0.f, 0.f);
        {
            const float4* qlo = p + (t0 - Pn) * C4;           // 26 rows
            const float4* qhi = p + (t0 + 224) * C4;          // 27 rows
            const float4* tq  = ts + (2 * s - 7) * C4;        // 14 tiles

            #pragma unroll
            for (int u = 0; u < 26; u++) {
                float4 v = qlo[u * C4];
                if      ((u & 3) == 0) acc4(a0, v);
                else if ((u & 3) == 1) acc4(a1, v);
                else if ((u & 3) == 2) acc4(a2, v);
                else                   acc4(a3, v);
            }
            #pragma unroll
            for (int u = 0; u < 27; u++) {
                float4 v = qhi[u * C4];
                if      ((u & 3) == 0) acc4(a0, v);
                else if ((u & 3) == 1) acc4(a1, v);
                else if ((u & 3) == 2) acc4(a2, v);
                else                   acc4(a3, v);
            }
            #pragma unroll
            for (int u = 0; u < 14; u++) {
                float4 v = tq[u * C4];
                if      ((u & 3) == 0) acc4(a0, v);
                else if ((u & 3) == 1) acc4(a1, v);
                else if ((u & 3) == 2) acc4(a2, v);
                else                   acc4(a3, v);
            }
        }
        W.x = (a0.x + a1.x) + (a2.x + a3.x);
        W.y = (a0.y + a1.y) + (a2.y + a3.y);
        W.z = (a0.z + a1.z) + (a2.z + a3.z);
        W.w = (a0.w + a1.w) + (a2.w + a3.w);

        const float4* lead  = p + (t0 + Pn + 1) * C4;
        const float4* trail = p + (t0 - Pn) * C4;
        const float4* mid   = p + t0 * C4;
        float4*       op    = o + t0 * C4;

        // ---- steady: 16 batches of 4 outputs, 12 loads issued up front ----
        for (int ii = 0; ii < SEG; ii += 4) {
            float4 L[4], Tt[4], M[4];
            #pragma unroll
            for (int j = 0; j < 4; j++) {
                L[j]  = lead [(ii + j) * C4];
                Tt[j] = trail[(ii + j) * C4];
                M[j]  = mid  [(ii + j) * C4];
            }
            #pragma unroll
            for (int j = 0; j < 4; j++) {
                float4 r;
                r.x = fmaxf(M[j].x, (W.x + bv) * inv);
                r.y = fmaxf(M[j].y, (W.y + bv) * inv);
                r.z = fmaxf(M[j].z, (W.z + bv) * inv);
                r.w = fmaxf(M[j].w, (W.w + bv) * inv);
                op[(ii + j) * C4] = r;
                W.x += L[j].x - Tt[j].x;
                W.y += L[j].y - Tt[j].y;
                W.z += L[j].z - Tt[j].z;
                W.w += L[j].w - Tt[j].w;
            }
        }
    } else {
        // ---- boundary path: init via contiguous range sums ----
        // win(t0) = sum_{k=t0-250}^{t0+250} x[refl(k)]
        //   k<0   maps to rows [1, 1-lo)          (forward range)
        //   k>=Tn maps to rows [2Tn-1-hi, Tn-1)   (forward range)
        W = make_float4(0.f, 0.f, 0.f, 0.f);
        int lo = t0 - Pn, hi = t0 + Pn + 1;
        if (lo < 0)  { range_sum(p, ts, 1, 1 - lo, W);            lo = 0;  }
        if (hi > Tn) { range_sum(p, ts, 2 * Tn - 1 - hi, Tn - 1, W); hi = Tn; }
        range_sum(p, ts, lo, hi, W);

        for (int ii = 0; ii < SEG; ii += 4) {
            float4 L[4], Tt[4], M[4];
            #pragma unroll
            for (int j = 0; j < 4; j++) {
                int t = t0 + ii + j;
                L[j]  = p[refl(t + Pn + 1) * C4];
                Tt[j] = p[refl(t - Pn) * C4];
                M[j]  = p[t * C4];
            }
            #pragma unroll
            for (int j = 0; j < 4; j++) {
                float4 r;
                r.x = fmaxf(M[j].x, (W.x + bv) * inv);
                r.y = fmaxf(M[j].y, (W.y + bv) * inv);
                r.z = fmaxf(M[j].z, (W.z + bv) * inv);
                r.w = fmaxf(M[j].w, (W.w + bv) * inv);
                o[(t0 + ii + j) * C4] = r;
                W.x += L[j].x - Tt[j].x;
                W.y += L[j].y - Tt[j].y;
                W.z += L[j].z - Tt[j].z;
                W.w += L[j].w - Tt[j].w;
            }
        }
    }
}

extern "C" void kernel_launch(void* const* d_in, const int* in_sizes, int n_in,
                              void* d_out, int out_size)
{
    const float4* pred = (const float4*)d_in[0];
    const float*  bias = (const float*)d_in[1];
    float4*       out  = (float4*)d_out;

    (void)in_sizes; (void)n_in; (void)out_size;

    dim3 g1(NT / WPB, Bn);     // 128 x 8 blocks, 4 tiles each
    dim3 g2(NSEG / WPB, Bn);   // 64 x 8 blocks, 4 segments each
    dim3 blk(32 * WPB);        // 128 threads
    tile_sum_kernel<<<g1, blk>>>(pred);
    smoother_kernel<<<g2, blk>>>(pred, bias, out);
}

// round 10
// speedup vs baseline: 1.9376x; 1.0746x over previous
#include <cuda_runtime.h>

// Smoother: out = max(pred, (moving_sum_501(reflect_pad_T(pred)) + bias) / 501)
// pred: [B=8, T=16384, C=128] fp32, bias: [1] fp32, out: same shape.
//
// R9: occupancy + cheaper init.
//  - SEG=32 -> 4096 warps; __launch_bounds__(128,6) caps regs ~85 so ~24
//    warps/SM are resident (R8: 14 warps/SM, latency-bound at DRAM=46%).
//  - init via OVER-covering tile sums: 16 tiles spanning [t0-256,t0+256)
//    minus 11 surplus rows = 27 loads per 32 outputs (R8: 67 per 64).

#define Bn   8
#define Tn   16384
#define C4   32            // 128 channels / 4 per float4
#define Kn   501
#define Pn   250
#define SEG  32
#define NSEG (Tn / SEG)    // 512
#define TILE 32
#define NT   (Tn / TILE)   // 512
#define WPB  4             // warps per block

// tile-sum scratch: 8 * 512 * 32 float4 = 2 MB
__device__ float4 g_TS[Bn * NT * C4];

__device__ __forceinline__ int refl(int k) {
    if (k < 0) k = -k;
    if (k >= Tn) k = 2 * Tn - 2 - k;
    return k;
}

__device__ __forceinline__ void acc4(float4& a, const float4 v) {
    a.x += v.x; a.y += v.y; a.z += v.z; a.w += v.w;
}
__device__ __forceinline__ void sub4(float4& a, const float4 v) {
    a.x -= v.x; a.y -= v.y; a.z -= v.z; a.w -= v.w;
}

// ---------------------------------------------------------------- kernel 1
__global__ void __launch_bounds__(128) tile_sum_kernel(
    const float4* __restrict__ pred)
{
    const int c = threadIdx.x & 31;
    const int w = threadIdx.x >> 5;
    const int j = blockIdx.x * WPB + w;      // tile 0..NT-1
    const int b = blockIdx.y;

    const float4* p = pred + ((size_t)b * Tn + (size_t)j * TILE) * C4 + c;

    float4 a0 = make_float4(0.f, 0.f, 0.f, 0.f);
    float4 a1 = make_float4(0.f, 0.f, 0.f, 0.f);
    float4 a2 = make_float4(0.f, 0.f, 0.f, 0.f);
    float4 a3 = make_float4(0.f, 0.f, 0.f, 0.f);

    #pragma unroll
    for (int base = 0; base < TILE; base += 8) {
        float4 r[8];
        #pragma unroll
        for (int u = 0; u < 8; u++) r[u] = p[(base + u) * C4];
        #pragma unroll
        for (int u = 0; u < 8; u += 4) {
            acc4(a0, r[u + 0]); acc4(a1, r[u + 1]);
            acc4(a2, r[u + 2]); acc4(a3, r[u + 3]);
        }
    }

    float4 s;
    s.x = (a0.x + a1.x) + (a2.x + a3.x);
    s.y = (a0.y + a1.y) + (a2.y + a3.y);
    s.z = (a0.z + a1.z) + (a2.z + a3.z);
    s.w = (a0.w + a1.w) + (a2.w + a3.w);

    g_TS[((size_t)b * NT + j) * C4 + c] = s;
}

// Sum rows [lo, hi) of column p (stride C4) using tile sums ts where possible.
__device__ __forceinline__ void range_sum(
    const float4* __restrict__ p, const float4* __restrict__ ts,
    int lo, int hi, float4& W)
{
    int jlo = (lo + TILE - 1) / TILE;
    int jhi = hi / TILE;
    if (jhi > jlo) {
        for (int r = lo; r < jlo * TILE; r++) acc4(W, p[r * C4]);
        #pragma unroll 4
        for (int j = jlo; j < jhi; j++)       acc4(W, ts[j * C4]);
        for (int r = jhi * TILE; r < hi; r++) acc4(W, p[r * C4]);
    } else {
        for (int r = lo; r < hi; r++) acc4(W, p[r * C4]);
    }
}

// ---------------------------------------------------------------- kernel 2
__global__ void __launch_bounds__(128, 6) smoother_kernel(
    const float4* __restrict__ pred,
    const float*  __restrict__ bias,
    float4*       __restrict__ out)
{
    const int c  = threadIdx.x & 31;        // float4 lane
    const int w  = threadIdx.x >> 5;        // warp in block
    const int s  = blockIdx.x * WPB + w;    // segment 0..NSEG-1
    const int b  = blockIdx.y;
    const int t0 = s * SEG;

    const float4* p  = pred + (size_t)b * Tn * C4 + c;
    float4*       o  = out  + (size_t)b * Tn * C4 + c;
    const float4* ts = g_TS + (size_t)b * NT * C4 + c;

    const float bv  = bias[0];
    const float inv = 1.0f / (float)Kn;

    float4 W;

    // Fast path: tiles s-8..s+7 valid AND steady footprint in-bounds:
    //   s >= 8  and  t0 + SEG + Pn + 1 <= Tn  (s <= 503)
    const bool fast = (s >= 8) && (t0 + SEG + Pn + 1 <= Tn);

    if (fast) {
        // ---- init: sum(tiles s-8..s+7)  [rows t0-256 .. t0+255]
        //            - rows [t0-256, t0-251]  (6 surplus low)
        //            - rows [t0+251, t0+255]  (5 surplus high)
        float4 a0 = make_float4(0.f, 0.f, 0.f, 0.f);
        float4 a1 = make_float4(0.f, 0.f, 0.f, 0.f);
        float4 a2 = make_float4(0.f, 0.f, 0.f, 0.f);
        float4 a3 = make_float4(0.f, 0.f, 0.f, 0.f);
        {
            const float4* tq = ts + (s - 8) * C4;          // 16 tiles
            #pragma unroll
            for (int base = 0; base < 16; base += 8) {
                float4 r[8];
                #pragma unroll
                for (int u = 0; u < 8; u++) r[u] = tq[(base + u) * C4];
                #pragma unroll
                for (int u = 0; u < 8; u += 4) {
                    acc4(a0, r[u + 0]); acc4(a1, r[u + 1]);
                    acc4(a2, r[u + 2]); acc4(a3, r[u + 3]);
                }
            }
            const float4* qlo = p + (t0 - 256) * C4;       // 6 rows
            const float4* qhi = p + (t0 + Pn + 1) * C4;    // 5 rows
            float4 e[11];
            #pragma unroll
            for (int u = 0; u < 6; u++) e[u]     = qlo[u * C4];
            #pragma unroll
            for (int u = 0; u < 5; u++) e[6 + u] = qhi[u * C4];
            #pragma unroll
            for (int u = 0; u < 11; u++) {
                if      ((u & 3) == 0) sub4(a0, e[u]);
                else if ((u & 3) == 1) sub4(a1, e[u]);
                else if ((u & 3) == 2) sub4(a2, e[u]);
                else                   sub4(a3, e[u]);
            }
        }
        W.x = (a0.x + a1.x) + (a2.x + a3.x);
        W.y = (a0.y + a1.y) + (a2.y + a3.y);
        W.z = (a0.z + a1.z) + (a2.z + a3.z);
        W.w = (a0.w + a1.w) + (a2.w + a3.w);

        const float4* lead  = p + (t0 + Pn + 1) * C4;
        const float4* trail = p + (t0 - Pn) * C4;
        const float4* mid   = p + t0 * C4;
        float4*       op    = o + t0 * C4;

        // ---- steady: 8 batches of 4 outputs, 12 loads issued up front ----
        for (int ii = 0; ii < SEG; ii += 4) {
            float4 L[4], Tt[4], M[4];
            #pragma unroll
            for (int j = 0; j < 4; j++) {
                L[j]  = lead [(ii + j) * C4];
                Tt[j] = trail[(ii + j) * C4];
                M[j]  = mid  [(ii + j) * C4];
            }
            #pragma unroll
            for (int j = 0; j < 4; j++) {
                float4 r;
                r.x = fmaxf(M[j].x, (W.x + bv) * inv);
                r.y = fmaxf(M[j].y, (W.y + bv) * inv);
                r.z = fmaxf(M[j].z, (W.z + bv) * inv);
                r.w = fmaxf(M[j].w, (W.w + bv) * inv);
                op[(ii + j) * C4] = r;
                W.x += L[j].x - Tt[j].x;
                W.y += L[j].y - Tt[j].y;
                W.z += L[j].z - Tt[j].z;
                W.w += L[j].w - Tt[j].w;
            }
        }
    } else {
        // ---- boundary path: init via contiguous range sums ----
        // win(t0) = sum_{k=t0-250}^{t0+250} x[refl(k)]
        //   k<0   maps to rows [1, 1-lo)
        //   k>=Tn maps to rows [2Tn-1-hi, Tn-1)
        W = make_float4(0.f, 0.f, 0.f, 0.f);
        int lo = t0 - Pn, hi = t0 + Pn + 1;
        if (lo < 0)  { range_sum(p, ts, 1, 1 - lo, W);               lo = 0;  }
        if (hi > Tn) { range_sum(p, ts, 2 * Tn - 1 - hi, Tn - 1, W); hi = Tn; }
        range_sum(p, ts, lo, hi, W);

        for (int ii = 0; ii < SEG; ii += 4) {
            float4 L[4], Tt[4], M[4];
            #pragma unroll
            for (int j = 0; j < 4; j++) {
                int t = t0 + ii + j;
                L[j]  = p[refl(t + Pn + 1) * C4];
                Tt[j] = p[refl(t - Pn) * C4];
                M[j]  = p[t * C4];
            }
            #pragma unroll
            for (int j = 0; j < 4; j++) {
                float4 r;
                r.x = fmaxf(M[j].x, (W.x + bv) * inv);
                r.y = fmaxf(M[j].y, (W.y + bv) * inv);
                r.z = fmaxf(M[j].z, (W.z + bv) * inv);
                r.w = fmaxf(M[j].w, (W.w + bv) * inv);
                o[(t0 + ii + j) * C4] = r;
                W.x += L[j].x - Tt[j].x;
                W.y += L[j].y - Tt[j].y;
                W.z += L[j].z - Tt[j].z;
                W.w += L[j].w - Tt[j].w;
            }
        }
    }
}

extern "C" void kernel_launch(void* const* d_in, const int* in_sizes, int n_in,
                              void* d_out, int out_size)
{
    const float4* pred = (const float4*)d_in[0];
    const float*  bias = (const float*)d_in[1];
    float4*       out  = (float4*)d_out;

    (void)in_sizes; (void)n_in; (void)out_size;

    dim3 g1(NT / WPB, Bn);     // 128 x 8 blocks, 4 tiles each
    dim3 g2(NSEG / WPB, Bn);   // 128 x 8 blocks, 4 segments each
    dim3 blk(32 * WPB);        // 128 threads
    tile_sum_kernel<<<g1, blk>>>(pred);
    smoother_kernel<<<g2, blk>>>(pred, bias, out);
}